// round 1
// baseline (speedup 1.0000x reference)
#include <cuda_runtime.h>
#include <cstdint>

#define NN 100000
#define EE 1600000

// ---------------- scratch (static device allocations, allowed) ----------------
__device__ int   g_counts[NN];
__device__ int   g_row[NN + 1];
__device__ int   g_cursor[NN];
__device__ float g_dinv[NN];
__device__ int   g_csrc[EE];
__device__ float g_bufA[(size_t)NN * 128];
__device__ float g_bufB[(size_t)NN * 128];
__device__ float g_bufC[(size_t)NN * 16];

// ---------------- CSR build ----------------
__global__ void k_zero_counts() {
    int i = blockIdx.x * blockDim.x + threadIdx.x;
    if (i < NN) g_counts[i] = 0;
}

__global__ void k_hist(const int* __restrict__ dst) {
    int e = blockIdx.x * blockDim.x + threadIdx.x;
    if (e < EE) atomicAdd(&g_counts[dst[e]], 1);
}

// single-block exclusive scan over counts -> row offsets, cursors, dinv
__global__ void k_scan() {
    __shared__ int part[1024];
    const int CH = (NN + 1023) / 1024;  // 98
    int t = threadIdx.x;
    int beg = t * CH;
    int end = beg + CH; if (end > NN) end = NN;
    int s = 0;
    for (int i = beg; i < end; i++) s += g_counts[i];
    part[t] = s;
    __syncthreads();
    // inclusive Hillis-Steele scan
    for (int off = 1; off < 1024; off <<= 1) {
        int v = (t >= off) ? part[t - off] : 0;
        __syncthreads();
        part[t] += v;
        __syncthreads();
    }
    int run = (t == 0) ? 0 : part[t - 1];
    for (int i = beg; i < end; i++) {
        int c = g_counts[i];
        g_row[i] = run;
        g_cursor[i] = run;
        g_dinv[i] = rsqrtf((float)(c + 1));  // +1 self loop
        run += c;
    }
    if (t == 1023) g_row[NN] = part[1023];
}

__global__ void k_scatter(const int* __restrict__ src, const int* __restrict__ dst) {
    int e = blockIdx.x * blockDim.x + threadIdx.x;
    if (e < EE) {
        int d = dst[e];
        int p = atomicAdd(&g_cursor[d], 1);
        g_csrc[p] = src[e];
    }
}

// ---------------- SGEMM: C[M,128] = A[M,K] * B[K,128] ----------------
template <int K>
__global__ __launch_bounds__(256) void sgemm128(
    const float* __restrict__ A, const float* __restrict__ B,
    float* __restrict__ C, int M)
{
    const int BM = 128, BN = 128, BK = 8, TM = 8, TN = 8;
    __shared__ float As[BK][BM];
    __shared__ float Bs[BK][BN];

    int tid = threadIdx.x;                // 256 threads
    int rowBase = blockIdx.x * BM;

    int aRow = tid >> 1;                  // 0..127
    int aCol = (tid & 1) * 4;             // 0 or 4
    int bRow = tid >> 5;                  // 0..7
    int bCol = (tid & 31) * 4;            // 0..124
    int tRow = (tid >> 4) * TM;           // 0..120
    int tCol = (tid & 15) * TN;           // 0..120

    float acc[TM][TN];
#pragma unroll
    for (int i = 0; i < TM; i++)
#pragma unroll
        for (int j = 0; j < TN; j++) acc[i][j] = 0.f;

    for (int k0 = 0; k0 < K; k0 += BK) {
        float4 a;
        int gr = rowBase + aRow;
        if (gr < M) a = *(const float4*)(A + (size_t)gr * K + k0 + aCol);
        else        a = make_float4(0.f, 0.f, 0.f, 0.f);
        As[aCol + 0][aRow] = a.x;
        As[aCol + 1][aRow] = a.y;
        As[aCol + 2][aRow] = a.z;
        As[aCol + 3][aRow] = a.w;

        float4 b = *(const float4*)(B + (size_t)(k0 + bRow) * BN + bCol);
        *(float4*)(&Bs[bRow][bCol]) = b;
        __syncthreads();

#pragma unroll
        for (int k = 0; k < BK; k++) {
            float regM[TM], regN[TN];
            *(float4*)(&regM[0]) = *(const float4*)(&As[k][tRow]);
            *(float4*)(&regM[4]) = *(const float4*)(&As[k][tRow + 4]);
            *(float4*)(&regN[0]) = *(const float4*)(&Bs[k][tCol]);
            *(float4*)(&regN[4]) = *(const float4*)(&Bs[k][tCol + 4]);
#pragma unroll
            for (int i = 0; i < TM; i++)
#pragma unroll
                for (int j = 0; j < TN; j++)
                    acc[i][j] = fmaf(regM[i], regN[j], acc[i][j]);
        }
        __syncthreads();
    }

#pragma unroll
    for (int i = 0; i < TM; i++) {
        int gr = rowBase + tRow + i;
        if (gr < M) {
            float4 v0 = make_float4(acc[i][0], acc[i][1], acc[i][2], acc[i][3]);
            float4 v1 = make_float4(acc[i][4], acc[i][5], acc[i][6], acc[i][7]);
            *(float4*)(C + (size_t)gr * 128 + tCol)     = v0;
            *(float4*)(C + (size_t)gr * 128 + tCol + 4) = v1;
        }
    }
}

// ---------------- small GEMM: C[M,16] = A[M,128] * W[128,16] ----------------
__global__ __launch_bounds__(256) void gemm16(
    const float* __restrict__ A, const float* __restrict__ W,
    float* __restrict__ C, int M)
{
    __shared__ float xs[64][132];   // pad for alignment + bank spread
    __shared__ float ws[128][16];

    int tid = threadIdx.x;
    int r0 = blockIdx.x * 64;

    // load x tile: 64 rows x 128 cols = 2048 float4
    for (int i = tid; i < 2048; i += 256) {
        int row = i >> 5;           // 32 float4 per row
        int c4 = i & 31;
        int gr = r0 + row;
        float4 v = (gr < M) ? *(const float4*)(A + (size_t)gr * 128 + c4 * 4)
                            : make_float4(0.f, 0.f, 0.f, 0.f);
        *(float4*)(&xs[row][c4 * 4]) = v;
    }
    // load W: 2048 scalars
    for (int i = tid; i < 2048; i += 256) ws[i >> 4][i & 15] = W[i];
    __syncthreads();

    int col = tid & 15;
    int rq  = tid >> 4;             // 0..15, owns rows rq*4..rq*4+3
    float acc[4] = {0.f, 0.f, 0.f, 0.f};
    for (int k = 0; k < 128; k++) {
        float w = ws[k][col];
#pragma unroll
        for (int r = 0; r < 4; r++)
            acc[r] = fmaf(xs[rq * 4 + r][k], w, acc[r]);
    }
#pragma unroll
    for (int r = 0; r < 4; r++) {
        int gr = r0 + rq * 4 + r;
        if (gr < M) C[(size_t)gr * 16 + col] = acc[r];
    }
}

// ---------------- aggregation, F=128: warp per node, float4 per lane ----------------
template <bool RELU>
__global__ __launch_bounds__(256) void agg128(
    const float4* __restrict__ h, const float* __restrict__ bias,
    float4* __restrict__ out)
{
    int warp = (blockIdx.x * blockDim.x + threadIdx.x) >> 5;
    int lane = threadIdx.x & 31;
    if (warp >= NN) return;
    int v = warp;

    float dv = g_dinv[v];
    float4 self = h[(size_t)v * 32 + lane];
    float4 acc;
    acc.x = dv * self.x; acc.y = dv * self.y;
    acc.z = dv * self.z; acc.w = dv * self.w;

    int rs = g_row[v], re = g_row[v + 1];
    int base = rs;
    for (; base + 32 <= re; base += 32) {
        int   s = g_csrc[base + lane];
        float d = g_dinv[s];
#pragma unroll
        for (int j = 0; j < 32; j++) {
            int   sj = __shfl_sync(0xffffffffu, s, j);
            float dj = __shfl_sync(0xffffffffu, d, j);
            float4 hv = h[(size_t)sj * 32 + lane];
            acc.x = fmaf(dj, hv.x, acc.x);
            acc.y = fmaf(dj, hv.y, acc.y);
            acc.z = fmaf(dj, hv.z, acc.z);
            acc.w = fmaf(dj, hv.w, acc.w);
        }
    }
    if (base < re) {
        int cnt = re - base;
        int   s = (lane < cnt) ? g_csrc[base + lane] : 0;
        float d = (lane < cnt) ? g_dinv[s] : 0.f;
        for (int j = 0; j < cnt; j++) {
            int   sj = __shfl_sync(0xffffffffu, s, j);
            float dj = __shfl_sync(0xffffffffu, d, j);
            float4 hv = h[(size_t)sj * 32 + lane];
            acc.x = fmaf(dj, hv.x, acc.x);
            acc.y = fmaf(dj, hv.y, acc.y);
            acc.z = fmaf(dj, hv.z, acc.z);
            acc.w = fmaf(dj, hv.w, acc.w);
        }
    }

    float4 bb = *(const float4*)(bias + 4 * lane);
    acc.x = fmaf(acc.x, dv, bb.x);
    acc.y = fmaf(acc.y, dv, bb.y);
    acc.z = fmaf(acc.z, dv, bb.z);
    acc.w = fmaf(acc.w, dv, bb.w);
    if (RELU) {
        acc.x = fmaxf(acc.x, 0.f); acc.y = fmaxf(acc.y, 0.f);
        acc.z = fmaxf(acc.z, 0.f); acc.w = fmaxf(acc.w, 0.f);
    }
    out[(size_t)v * 32 + lane] = acc;
}

// ---------------- aggregation, F=16: warp per node, scalar (lanes 0..15) ----------------
__global__ __launch_bounds__(256) void agg16(
    const float* __restrict__ h, const float* __restrict__ bias,
    float* __restrict__ out)
{
    int warp = (blockIdx.x * blockDim.x + threadIdx.x) >> 5;
    int lane = threadIdx.x & 31;
    if (warp >= NN) return;
    int v = warp;

    float dv = g_dinv[v];
    float acc = (lane < 16) ? dv * h[(size_t)v * 16 + lane] : 0.f;

    int rs = g_row[v], re = g_row[v + 1];
    int base = rs;
    for (; base + 32 <= re; base += 32) {
        int   s = g_csrc[base + lane];
        float d = g_dinv[s];
#pragma unroll
        for (int j = 0; j < 32; j++) {
            int   sj = __shfl_sync(0xffffffffu, s, j);
            float dj = __shfl_sync(0xffffffffu, d, j);
            if (lane < 16) acc = fmaf(dj, h[(size_t)sj * 16 + lane], acc);
        }
    }
    if (base < re) {
        int cnt = re - base;
        int   s = (lane < cnt) ? g_csrc[base + lane] : 0;
        float d = (lane < cnt) ? g_dinv[s] : 0.f;
        for (int j = 0; j < cnt; j++) {
            int   sj = __shfl_sync(0xffffffffu, s, j);
            float dj = __shfl_sync(0xffffffffu, d, j);
            if (lane < 16) acc = fmaf(dj, h[(size_t)sj * 16 + lane], acc);
        }
    }

    if (lane < 16) {
        acc = fmaf(acc, dv, bias[lane]);
        out[(size_t)v * 16 + lane] = acc;
    }
}

// ---------------- launch ----------------
extern "C" void kernel_launch(void* const* d_in, const int* in_sizes, int n_in,
                              void* d_out, int out_size)
{
    const float* x  = (const float*)d_in[0];
    const int*   ei = (const int*)d_in[1];      // [2, E]: first E = src, next E = dst
    const float* W1 = (const float*)d_in[2];
    const float* b1 = (const float*)d_in[3];
    const float* W2 = (const float*)d_in[4];
    const float* b2 = (const float*)d_in[5];
    const float* W3 = (const float*)d_in[6];
    const float* b3 = (const float*)d_in[7];
    float* out = (float*)d_out;

    float *pA = nullptr, *pB = nullptr, *pC = nullptr;
    cudaGetSymbolAddress((void**)&pA, g_bufA);
    cudaGetSymbolAddress((void**)&pB, g_bufB);
    cudaGetSymbolAddress((void**)&pC, g_bufC);

    const int* e_src = ei;
    const int* e_dst = ei + EE;

    // CSR build (per call; graph-captured)
    k_zero_counts<<<(NN + 255) / 256, 256>>>();
    k_hist<<<(EE + 255) / 256, 256>>>(e_dst);
    k_scan<<<1, 1024>>>();
    k_scatter<<<(EE + 255) / 256, 256>>>(e_src, e_dst);

    const int AGG_BLOCKS = (NN + 7) / 8;  // 8 warps per 256-thread block

    // Layer 1: h = relu(agg(x @ W1) + b1)
    sgemm128<256><<<(NN + 127) / 128, 256>>>(x, W1, pA, NN);
    agg128<true><<<AGG_BLOCKS, 256>>>((const float4*)pA, b1, (float4*)pB);

    // Layer 2
    sgemm128<128><<<(NN + 127) / 128, 256>>>(pB, W2, pA, NN);
    agg128<true><<<AGG_BLOCKS, 256>>>((const float4*)pA, b2, (float4*)pB);

    // Layer 3 (no relu)
    gemm16<<<(NN + 63) / 64, 256>>>(pB, W3, pC, NN);
    agg16<<<AGG_BLOCKS, 256>>>(pC, b3, out);
}

// round 2
// speedup vs baseline: 1.1249x; 1.1249x over previous
#include <cuda_runtime.h>
#include <cuda_bf16.h>
#include <mma.h>
#include <cstdint>

using namespace nvcuda;

#define NN 100000
#define EE 1600000
#define MPAD 100096   // 782 * 128

// ---------------- scratch (static device allocations, allowed) ----------------
__device__ int   g_counts[NN];
__device__ int   g_row[NN + 1];
__device__ int   g_cursor[NN];
__device__ float g_dinv[NN];
__device__ int   g_csrc[EE];

__device__ float          g_h[(size_t)MPAD * 128];       // GEMM fp32 output (agg input)
__device__ float          g_hb[(size_t)MPAD * 128];      // layer2 agg fp32 output
__device__ float          g_c16[(size_t)MPAD * 16];      // layer3 gemm output
__device__ __nv_bfloat16  g_xh[(size_t)MPAD * 256];      // x split hi
__device__ __nv_bfloat16  g_xl[(size_t)MPAD * 256];      // x split lo
__device__ __nv_bfloat16  g_ah[(size_t)MPAD * 128];      // h split hi (layer2 A)
__device__ __nv_bfloat16  g_al[(size_t)MPAD * 128];      // h split lo
__device__ __nv_bfloat16  g_w1h[256 * 128], g_w1l[256 * 128];
__device__ __nv_bfloat16  g_w2h[128 * 128], g_w2l[128 * 128];

// ---------------- helpers ----------------
__device__ __forceinline__ void split4(float4 v, uint2& hi, uint2& lo) {
    __align__(8) __nv_bfloat16 h[4], l[4];
    float f[4] = {v.x, v.y, v.z, v.w};
#pragma unroll
    for (int i = 0; i < 4; i++) {
        h[i] = __float2bfloat16_rn(f[i]);
        l[i] = __float2bfloat16_rn(f[i] - __bfloat162float(h[i]));
    }
    hi = *(uint2*)h;
    lo = *(uint2*)l;
}

__global__ void k_split(const float* __restrict__ A,
                        __nv_bfloat16* __restrict__ H,
                        __nv_bfloat16* __restrict__ L, int n4) {
    int i = blockIdx.x * blockDim.x + threadIdx.x;
    if (i < n4) {
        float4 v = ((const float4*)A)[i];
        uint2 h, l;
        split4(v, h, l);
        ((uint2*)H)[i] = h;
        ((uint2*)L)[i] = l;
    }
}

// ---------------- CSR build ----------------
__global__ void k_zero_counts() {
    int i = blockIdx.x * blockDim.x + threadIdx.x;
    if (i < NN) g_counts[i] = 0;
}

__global__ void k_hist(const int* __restrict__ dst) {
    int e = blockIdx.x * blockDim.x + threadIdx.x;
    if (e < EE) atomicAdd(&g_counts[dst[e]], 1);
}

__global__ void k_scan() {
    __shared__ int part[1024];
    const int CH = (NN + 1023) / 1024;
    int t = threadIdx.x;
    int beg = t * CH;
    int end = beg + CH; if (end > NN) end = NN;
    int s = 0;
    for (int i = beg; i < end; i++) s += g_counts[i];
    part[t] = s;
    __syncthreads();
    for (int off = 1; off < 1024; off <<= 1) {
        int v = (t >= off) ? part[t - off] : 0;
        __syncthreads();
        part[t] += v;
        __syncthreads();
    }
    int run = (t == 0) ? 0 : part[t - 1];
    for (int i = beg; i < end; i++) {
        int c = g_counts[i];
        g_row[i] = run;
        g_cursor[i] = run;
        g_dinv[i] = rsqrtf((float)(c + 1));
        run += c;
    }
    if (t == 1023) g_row[NN] = part[1023];
}

__global__ void k_scatter(const int* __restrict__ src, const int* __restrict__ dst) {
    int e = blockIdx.x * blockDim.x + threadIdx.x;
    if (e < EE) {
        int d = dst[e];
        int p = atomicAdd(&g_cursor[d], 1);
        g_csrc[p] = src[e];
    }
}

// ---------------- tensor-core GEMM (split-bf16): C[MPAD,128] = A[MPAD,K] * B[K,128] ----------------
// A given as (Ah + Al), B as (Bh + Bl); compute Ah*Bh + Al*Bh + Ah*Bl in fp32 accum.
template <int K>
__global__ __launch_bounds__(256) void wgemm128(
    const __nv_bfloat16* __restrict__ Ah, const __nv_bfloat16* __restrict__ Al,
    const __nv_bfloat16* __restrict__ Bh, const __nv_bfloat16* __restrict__ Bl,
    float* __restrict__ C)
{
    constexpr int KC  = 32;
    constexpr int LDA = KC + 8;    // 40, mult of 8
    constexpr int LDB = 128 + 8;   // 136, mult of 8
    __shared__ __nv_bfloat16 sAh[128 * LDA];
    __shared__ __nv_bfloat16 sAl[128 * LDA];
    __shared__ __nv_bfloat16 sBh[KC * LDB];
    __shared__ __nv_bfloat16 sBl[KC * LDB];

    int tid  = threadIdx.x;
    int warp = tid >> 5;
    int wm   = warp >> 1;    // 0..3 -> 32-row slab
    int wn   = warp & 1;     // 0..1 -> 64-col slab
    size_t rowBase = (size_t)blockIdx.x * 128;

    wmma::fragment<wmma::accumulator, 16, 16, 16, float> acc[2][4];
#pragma unroll
    for (int i = 0; i < 2; i++)
#pragma unroll
        for (int j = 0; j < 4; j++) wmma::fill_fragment(acc[i][j], 0.f);

    for (int k0 = 0; k0 < K; k0 += KC) {
        // A chunk: 128 x 32 bf16 (each buf) -> 512 uint4 per buf
#pragma unroll
        for (int i = tid; i < 512; i += 256) {
            int r = i >> 2, c8 = (i & 3) * 8;
            *(uint4*)&sAh[r * LDA + c8] = *(const uint4*)&Ah[(rowBase + r) * K + k0 + c8];
            *(uint4*)&sAl[r * LDA + c8] = *(const uint4*)&Al[(rowBase + r) * K + k0 + c8];
        }
        // B chunk: 32 x 128 bf16 -> 512 uint4 per buf
#pragma unroll
        for (int i = tid; i < 512; i += 256) {
            int r = i >> 4, c8 = (i & 15) * 8;
            *(uint4*)&sBh[r * LDB + c8] = *(const uint4*)&Bh[(size_t)(k0 + r) * 128 + c8];
            *(uint4*)&sBl[r * LDB + c8] = *(const uint4*)&Bl[(size_t)(k0 + r) * 128 + c8];
        }
        __syncthreads();

#pragma unroll
        for (int kk = 0; kk < KC; kk += 16) {
            wmma::fragment<wmma::matrix_a, 16, 16, 16, __nv_bfloat16, wmma::row_major> afh[2], afl[2];
#pragma unroll
            for (int i = 0; i < 2; i++) {
                int r = wm * 32 + i * 16;
                wmma::load_matrix_sync(afh[i], &sAh[r * LDA + kk], LDA);
                wmma::load_matrix_sync(afl[i], &sAl[r * LDA + kk], LDA);
            }
#pragma unroll
            for (int j = 0; j < 4; j++) {
                int c = wn * 64 + j * 16;
                wmma::fragment<wmma::matrix_b, 16, 16, 16, __nv_bfloat16, wmma::row_major> bfh, bfl;
                wmma::load_matrix_sync(bfh, &sBh[kk * LDB + c], LDB);
                wmma::load_matrix_sync(bfl, &sBl[kk * LDB + c], LDB);
#pragma unroll
                for (int i = 0; i < 2; i++) {
                    wmma::mma_sync(acc[i][j], afh[i], bfh, acc[i][j]);
                    wmma::mma_sync(acc[i][j], afl[i], bfh, acc[i][j]);
                    wmma::mma_sync(acc[i][j], afh[i], bfl, acc[i][j]);
                }
            }
        }
        __syncthreads();
    }

#pragma unroll
    for (int i = 0; i < 2; i++)
#pragma unroll
        for (int j = 0; j < 4; j++) {
            size_t r = rowBase + wm * 32 + i * 16;
            int c = wn * 64 + j * 16;
            wmma::store_matrix_sync(&C[r * 128 + c], acc[i][j], 128, wmma::mem_row_major);
        }
}

// ---------------- small GEMM: C[M,16] = A[M,128] * W[128,16] (fp32 SIMT) ----------------
__global__ __launch_bounds__(256) void gemm16(
    const float* __restrict__ A, const float* __restrict__ W,
    float* __restrict__ C, int M)
{
    __shared__ float xs[64][132];
    __shared__ float ws[128][16];

    int tid = threadIdx.x;
    int r0 = blockIdx.x * 64;

    for (int i = tid; i < 2048; i += 256) {
        int row = i >> 5;
        int c4 = i & 31;
        int gr = r0 + row;
        float4 v = (gr < M) ? *(const float4*)(A + (size_t)gr * 128 + c4 * 4)
                            : make_float4(0.f, 0.f, 0.f, 0.f);
        *(float4*)(&xs[row][c4 * 4]) = v;
    }
    for (int i = tid; i < 2048; i += 256) ws[i >> 4][i & 15] = W[i];
    __syncthreads();

    int col = tid & 15;
    int rq  = tid >> 4;
    float acc[4] = {0.f, 0.f, 0.f, 0.f};
    for (int k = 0; k < 128; k++) {
        float w = ws[k][col];
#pragma unroll
        for (int r = 0; r < 4; r++)
            acc[r] = fmaf(xs[rq * 4 + r][k], w, acc[r]);
    }
#pragma unroll
    for (int r = 0; r < 4; r++) {
        int gr = r0 + rq * 4 + r;
        if (gr < M) C[(size_t)gr * 16 + col] = acc[r];
    }
}

// ---------------- aggregation, F=128 ----------------
// SPLIT_OUT: write bf16 hi/lo (feeds next tensor-core GEMM); else fp32.
template <bool RELU, bool SPLIT_OUT>
__global__ __launch_bounds__(256) void agg128(
    const float4* __restrict__ h, const float* __restrict__ bias,
    float4* __restrict__ outF,
    __nv_bfloat16* __restrict__ outH, __nv_bfloat16* __restrict__ outL)
{
    int warp = (blockIdx.x * blockDim.x + threadIdx.x) >> 5;
    int lane = threadIdx.x & 31;
    if (warp >= NN) return;
    int v = warp;

    float dv = g_dinv[v];
    float4 self = h[(size_t)v * 32 + lane];
    float4 acc;
    acc.x = dv * self.x; acc.y = dv * self.y;
    acc.z = dv * self.z; acc.w = dv * self.w;

    int rs = g_row[v], re = g_row[v + 1];
    int base = rs;
    for (; base + 32 <= re; base += 32) {
        int   s = g_csrc[base + lane];
        float d = g_dinv[s];
#pragma unroll
        for (int j = 0; j < 32; j++) {
            int   sj = __shfl_sync(0xffffffffu, s, j);
            float dj = __shfl_sync(0xffffffffu, d, j);
            float4 hv = h[(size_t)sj * 32 + lane];
            acc.x = fmaf(dj, hv.x, acc.x);
            acc.y = fmaf(dj, hv.y, acc.y);
            acc.z = fmaf(dj, hv.z, acc.z);
            acc.w = fmaf(dj, hv.w, acc.w);
        }
    }
    if (base < re) {
        int cnt = re - base;
        int   s = (lane < cnt) ? g_csrc[base + lane] : 0;
        float d = (lane < cnt) ? g_dinv[s] : 0.f;
        for (int j = 0; j < cnt; j++) {
            int   sj = __shfl_sync(0xffffffffu, s, j);
            float dj = __shfl_sync(0xffffffffu, d, j);
            float4 hv = h[(size_t)sj * 32 + lane];
            acc.x = fmaf(dj, hv.x, acc.x);
            acc.y = fmaf(dj, hv.y, acc.y);
            acc.z = fmaf(dj, hv.z, acc.z);
            acc.w = fmaf(dj, hv.w, acc.w);
        }
    }

    float4 bb = *(const float4*)(bias + 4 * lane);
    acc.x = fmaf(acc.x, dv, bb.x);
    acc.y = fmaf(acc.y, dv, bb.y);
    acc.z = fmaf(acc.z, dv, bb.z);
    acc.w = fmaf(acc.w, dv, bb.w);
    if (RELU) {
        acc.x = fmaxf(acc.x, 0.f); acc.y = fmaxf(acc.y, 0.f);
        acc.z = fmaxf(acc.z, 0.f); acc.w = fmaxf(acc.w, 0.f);
    }
    if (SPLIT_OUT) {
        uint2 hi, lo;
        split4(acc, hi, lo);
        ((uint2*)outH)[(size_t)v * 32 + lane] = hi;
        ((uint2*)outL)[(size_t)v * 32 + lane] = lo;
    } else {
        outF[(size_t)v * 32 + lane] = acc;
    }
}

// ---------------- aggregation, F=16 ----------------
__global__ __launch_bounds__(256) void agg16(
    const float* __restrict__ h, const float* __restrict__ bias,
    float* __restrict__ out)
{
    int warp = (blockIdx.x * blockDim.x + threadIdx.x) >> 5;
    int lane = threadIdx.x & 31;
    if (warp >= NN) return;
    int v = warp;

    float dv = g_dinv[v];
    float acc = (lane < 16) ? dv * h[(size_t)v * 16 + lane] : 0.f;

    int rs = g_row[v], re = g_row[v + 1];
    int base = rs;
    for (; base + 32 <= re; base += 32) {
        int   s = g_csrc[base + lane];
        float d = g_dinv[s];
#pragma unroll
        for (int j = 0; j < 32; j++) {
            int   sj = __shfl_sync(0xffffffffu, s, j);
            float dj = __shfl_sync(0xffffffffu, d, j);
            if (lane < 16) acc = fmaf(dj, h[(size_t)sj * 16 + lane], acc);
        }
    }
    if (base < re) {
        int cnt = re - base;
        int   s = (lane < cnt) ? g_csrc[base + lane] : 0;
        float d = (lane < cnt) ? g_dinv[s] : 0.f;
        for (int j = 0; j < cnt; j++) {
            int   sj = __shfl_sync(0xffffffffu, s, j);
            float dj = __shfl_sync(0xffffffffu, d, j);
            if (lane < 16) acc = fmaf(dj, h[(size_t)sj * 16 + lane], acc);
        }
    }

    if (lane < 16) {
        acc = fmaf(acc, dv, bias[lane]);
        out[(size_t)v * 16 + lane] = acc;
    }
}

// ---------------- launch ----------------
extern "C" void kernel_launch(void* const* d_in, const int* in_sizes, int n_in,
                              void* d_out, int out_size)
{
    const float* x  = (const float*)d_in[0];
    const int*   ei = (const int*)d_in[1];
    const float* W1 = (const float*)d_in[2];
    const float* b1 = (const float*)d_in[3];
    const float* W2 = (const float*)d_in[4];
    const float* b2 = (const float*)d_in[5];
    const float* W3 = (const float*)d_in[6];
    const float* b3 = (const float*)d_in[7];
    float* out = (float*)d_out;

    float *pH = nullptr, *pHB = nullptr, *pC16 = nullptr;
    __nv_bfloat16 *pXH, *pXL, *pAH, *pAL, *pW1H, *pW1L, *pW2H, *pW2L;
    cudaGetSymbolAddress((void**)&pH,   g_h);
    cudaGetSymbolAddress((void**)&pHB,  g_hb);
    cudaGetSymbolAddress((void**)&pC16, g_c16);
    cudaGetSymbolAddress((void**)&pXH,  g_xh);
    cudaGetSymbolAddress((void**)&pXL,  g_xl);
    cudaGetSymbolAddress((void**)&pAH,  g_ah);
    cudaGetSymbolAddress((void**)&pAL,  g_al);
    cudaGetSymbolAddress((void**)&pW1H, g_w1h);
    cudaGetSymbolAddress((void**)&pW1L, g_w1l);
    cudaGetSymbolAddress((void**)&pW2H, g_w2h);
    cudaGetSymbolAddress((void**)&pW2L, g_w2l);

    const int* e_src = ei;
    const int* e_dst = ei + EE;

    // CSR build
    k_zero_counts<<<(NN + 255) / 256, 256>>>();
    k_hist<<<(EE + 255) / 256, 256>>>(e_dst);
    k_scan<<<1, 1024>>>();
    k_scatter<<<(EE + 255) / 256, 256>>>(e_src, e_dst);

    // splits
    {
        int n4 = NN * 256 / 4;
        k_split<<<(n4 + 255) / 256, 256>>>(x, pXH, pXL, n4);
        int w1n4 = 256 * 128 / 4;
        k_split<<<(w1n4 + 255) / 256, 256>>>(W1, pW1H, pW1L, w1n4);
        int w2n4 = 128 * 128 / 4;
        k_split<<<(w2n4 + 255) / 256, 256>>>(W2, pW2H, pW2L, w2n4);
    }

    const int AGG_BLOCKS = (NN + 7) / 8;
    const int GEMM_BLOCKS = MPAD / 128;  // 782

    // Layer 1
    wgemm128<256><<<GEMM_BLOCKS, 256>>>(pXH, pXL, pW1H, pW1L, pH);
    agg128<true, true><<<AGG_BLOCKS, 256>>>((const float4*)pH, b1, nullptr, pAH, pAL);

    // Layer 2
    wgemm128<128><<<GEMM_BLOCKS, 256>>>(pAH, pAL, pW2H, pW2L, pH);
    agg128<true, false><<<AGG_BLOCKS, 256>>>((const float4*)pH, b2, (float4*)pHB, nullptr, nullptr);

    // Layer 3
    gemm16<<<(NN + 63) / 64, 256>>>(pHB, W3, pC16, NN);
    agg16<<<AGG_BLOCKS, 256>>>(pC16, b3, out);
}